// round 11
// baseline (speedup 1.0000x reference)
#include <cuda_runtime.h>
#include <cuda_bf16.h>
#include <math.h>

#define BATCH   2
#define SEQ     2048
#define DMODEL  1024
#define HEADS   16
#define DK      64
#define MROWS   (BATCH * SEQ)      // 4096
#define ATS     68                 // attention smem row stride (floats)
#define ATTN_SMEM ((4 * 64 * ATS + 128) * 4)   // 70144 bytes

typedef unsigned long long ull;
typedef unsigned int u32;

// ---------------- packed f32x2 helpers (attention path) ----------------
__device__ __forceinline__ void ffma2(ull& d, ull a, ull b) {
    asm("fma.rn.f32x2 %0, %1, %2, %0;" : "+l"(d) : "l"(a), "l"(b));
}
__device__ __forceinline__ ull bcast2(float a) {
    ull r; asm("mov.b64 %0, {%1, %1};" : "=l"(r) : "f"(a)); return r;
}
__device__ __forceinline__ void mulf2(ull& d, ull a) {
    asm("mul.rn.f32x2 %0, %0, %1;" : "+l"(d) : "l"(a));
}
__device__ __forceinline__ float2 unpack2(ull v) {
    float2 f; asm("mov.b64 {%0, %1}, %2;" : "=f"(f.x), "=f"(f.y) : "l"(v)); return f;
}

// ---------------- warp-MMA helpers (baseline PTX, works on compute_103) ----
__device__ __forceinline__ u32 smem_u32(const void* p) {
    u32 a;
    asm("{ .reg .u64 t; cvta.to.shared.u64 t, %1; cvt.u32.u64 %0, t; }"
        : "=r"(a) : "l"(p));
    return a;
}
__device__ __forceinline__ void ldsm4(u32& r0, u32& r1, u32& r2, u32& r3, u32 addr) {
    asm volatile("ldmatrix.sync.aligned.m8n8.x4.shared.b16 {%0,%1,%2,%3}, [%4];"
                 : "=r"(r0), "=r"(r1), "=r"(r2), "=r"(r3) : "r"(addr));
}
__device__ __forceinline__ void mma16816(float* c, const u32* a, u32 b0, u32 b1) {
    asm volatile("mma.sync.aligned.m16n8k16.row.col.f32.bf16.bf16.f32 "
                 "{%0,%1,%2,%3}, {%4,%5,%6,%7}, {%8,%9}, {%0,%1,%2,%3};"
                 : "+f"(c[0]), "+f"(c[1]), "+f"(c[2]), "+f"(c[3])
                 : "r"(a[0]), "r"(a[1]), "r"(a[2]), "r"(a[3]), "r"(b0), "r"(b1));
}

// ---------------- scratch (device globals: allocation-free) ----------------
__device__ float g_Q[MROWS * DMODEL];
__device__ float g_K[MROWS * DMODEL];
__device__ float g_V[MROWS * DMODEL];
__device__ float g_ctx[MROWS * DMODEL];
__device__ float g_biasTab[HEADS * 4096];   // [h][rp + 2047]
__device__ __nv_bfloat16 g_Wth[4][DMODEL * DMODEL];  // W^T hi, [n][k]
__device__ __nv_bfloat16 g_Wtl[4][DMODEL * DMODEL];  // W^T lo, [n][k]

// ---------------- T5 relative-position bias table ----------------
__global__ void bias_table_kernel(const float* __restrict__ rel_bias) {
    int idx = blockIdx.x * blockDim.x + threadIdx.x;
    if (idx >= HEADS * 4095) return;
    int h  = idx / 4095;
    int i  = idx % 4095;
    int rp = i - 2047;
    int rb  = (rp > 0) ? 16 : 0;
    int rpa = rp < 0 ? -rp : rp;
    int bkt;
    if (rpa < 8) {
        bkt = rpa;
    } else {
        float t = logf((float)rpa * 0.125f);
        t = t / 2.7725887222397812f;
        t = t * 8.0f;
        bkt = 8 + (int)t;
        if (bkt > 15) bkt = 15;
    }
    g_biasTab[h * 4096 + i] = rel_bias[(rb + bkt) * HEADS + h];
}

// ---------------- weight transpose + bf16 hi/lo split prepass ----------------
__global__ void wconv_kernel(const float* __restrict__ Wq, const float* __restrict__ Wk,
                             const float* __restrict__ Wv, const float* __restrict__ Wo) {
    __shared__ float tile[32][33];
    int z = blockIdx.z;
    const float* W = (z == 0) ? Wq : (z == 1) ? Wk : (z == 2) ? Wv : Wo;
    __nv_bfloat16* Oh = g_Wth[z];
    __nv_bfloat16* Ol = g_Wtl[z];
    int x0 = blockIdx.x * 32, y0 = blockIdx.y * 32;
    int tx = threadIdx.x, ty = threadIdx.y;
#pragma unroll
    for (int i = 0; i < 4; i++)
        tile[ty + i * 8][tx] = W[(size_t)(y0 + ty + i * 8) * DMODEL + x0 + tx];
    __syncthreads();
#pragma unroll
    for (int i = 0; i < 4; i++) {
        float v = tile[tx][ty + i * 8];
        int n = x0 + ty + i * 8, k = y0 + tx;
        __nv_bfloat16 h = __float2bfloat16(v);
        float lo = v - __bfloat162float(h);
        Oh[(size_t)n * DMODEL + k] = h;
        Ol[(size_t)n * DMODEL + k] = __float2bfloat16(lo);
    }
}

// ---------------- MMA GEMM: C[4096,1024] = A(f32) @ W, 3-pass bf16 ----------
// smem: per stage 4 matrices [128 rows][40 bf16] (80B row stride, conflict-free
// for ldmatrix: 8 rows x 80B cover all 32 banks disjointly)
#define RSB     80                       // row stride bytes
#define MAT_SZ  (128 * RSB)              // 10240
#define STG_SZ  (4 * MAT_SZ)             // 40960
#define GEMM_SMEM (2 * STG_SZ)           // 81920

__device__ __forceinline__ void ldA_regs(float4* pa, const float* Ag,
                                         int t, int m0, int k0) {
#pragma unroll
    for (int u = 0; u < 4; u++) {
        int idx = t + u * 256;
        int row = idx >> 3, kq = idx & 7;
        pa[u] = *(const float4*)(Ag + (size_t)(m0 + row) * DMODEL + k0 + kq * 4);
    }
}
__device__ __forceinline__ void ldB_regs(uint2* pb, const __nv_bfloat16* Bg,
                                         int t, int n0, int k0) {
#pragma unroll
    for (int u = 0; u < 4; u++) {
        int idx = t + u * 256;
        int row = idx >> 3, kq = idx & 7;
        pb[u] = *(const uint2*)(Bg + (size_t)(n0 + row) * DMODEL + k0 + kq * 4);
    }
}
__device__ __forceinline__ void stA_smem(const float4* pa, char* dh, char* dl, int t) {
#pragma unroll
    for (int u = 0; u < 4; u++) {
        int idx = t + u * 256;
        int row = idx >> 3, kq = idx & 7;
        float4 v = pa[u];
        __nv_bfloat162 h0 = __floats2bfloat162_rn(v.x, v.y);
        __nv_bfloat162 h1 = __floats2bfloat162_rn(v.z, v.w);
        float2 f0 = __bfloat1622float2(h0);
        float2 f1 = __bfloat1622float2(h1);
        __nv_bfloat162 l0 = __floats2bfloat162_rn(v.x - f0.x, v.y - f0.y);
        __nv_bfloat162 l1 = __floats2bfloat162_rn(v.z - f1.x, v.w - f1.y);
        int off = row * RSB + kq * 8;
        *(__nv_bfloat162*)(dh + off)     = h0;
        *(__nv_bfloat162*)(dh + off + 4) = h1;
        *(__nv_bfloat162*)(dl + off)     = l0;
        *(__nv_bfloat162*)(dl + off + 4) = l1;
    }
}
__device__ __forceinline__ void stB_smem(const uint2* pb, char* d, int t) {
#pragma unroll
    for (int u = 0; u < 4; u++) {
        int idx = t + u * 256;
        int row = idx >> 3, kq = idx & 7;
        *(uint2*)(d + row * RSB + kq * 8) = pb[u];
    }
}

__device__ __forceinline__ void gemm_mma_body(
    const float* __restrict__ A,
    const __nv_bfloat16* __restrict__ Bh_g, const __nv_bfloat16* __restrict__ Bl_g,
    float* __restrict__ C, int bm, int bn)
{
    extern __shared__ char sm[];
    const u32 sb = smem_u32(sm);
    const int t = threadIdx.x, wid = t >> 5, lane = t & 31;
    const int wm = wid >> 1, wn = wid & 1;        // 4x2 warp grid
    const int m0 = bm * 128, n0 = bn * 128;

    float acc[2][8][4];
#pragma unroll
    for (int i = 0; i < 2; i++)
#pragma unroll
        for (int j = 0; j < 8; j++)
#pragma unroll
            for (int q = 0; q < 4; q++) acc[i][j][q] = 0.f;

    // lane decomposition for ldmatrix addressing
    const int r15 = lane & 15, kh = lane >> 4;                 // A tiles
    const int bn_lane = ((lane >> 4) << 3) + (lane & 7);       // B tiles
    const int bkh = (lane >> 3) & 1;

    float4 pa[4]; uint2 pbh[4], pbl[4];

    // preload + store chunk 0
    ldA_regs(pa, A, t, m0, 0);
    ldB_regs(pbh, Bh_g, t, n0, 0);
    ldB_regs(pbl, Bl_g, t, n0, 0);
    stA_smem(pa, sm, sm + MAT_SZ, t);
    stB_smem(pbh, sm + 2 * MAT_SZ, t);
    stB_smem(pbl, sm + 3 * MAT_SZ, t);
    __syncthreads();

    int cur = 0;
#pragma unroll 1
    for (int c = 0; c < DMODEL / 32; c++) {
        const bool more = (c + 1) < DMODEL / 32;
        if (more) {                       // issue next chunk's global loads early
            int k0n = (c + 1) * 32;
            ldA_regs(pa, A, t, m0, k0n);
            ldB_regs(pbh, Bh_g, t, n0, k0n);
            ldB_regs(pbl, Bl_g, t, n0, k0n);
        }

        const u32 stg = sb + cur * STG_SZ;
        const u32 a_h = stg, a_l = stg + MAT_SZ;
        const u32 b_h = stg + 2 * MAT_SZ, b_l = stg + 3 * MAT_SZ;

#pragma unroll
        for (int ks = 0; ks < 2; ks++) {
            const u32 kofA = (u32)((ks * 16 + kh * 8) * 2);
            const u32 kofB = (u32)((ks * 16 + bkh * 8) * 2);
            u32 ah[2][4], al[2][4];
#pragma unroll
            for (int mt = 0; mt < 2; mt++) {
                u32 ar = (u32)((wm * 32 + mt * 16 + r15) * RSB);
                ldsm4(ah[mt][0], ah[mt][1], ah[mt][2], ah[mt][3], a_h + ar + kofA);
                ldsm4(al[mt][0], al[mt][1], al[mt][2], al[mt][3], a_l + ar + kofA);
            }
#pragma unroll
            for (int np = 0; np < 4; np++) {         // each covers 16 n cols
                u32 br = (u32)((wn * 64 + np * 16 + bn_lane) * RSB);
                u32 h0, h1, h2, h3, l0, l1, l2, l3;
                ldsm4(h0, h1, h2, h3, b_h + br + kofB);
                ldsm4(l0, l1, l2, l3, b_l + br + kofB);
#pragma unroll
                for (int mt = 0; mt < 2; mt++) {
                    mma16816(acc[mt][np * 2],     ah[mt], h0, h1);   // hi*hi
                    mma16816(acc[mt][np * 2 + 1], ah[mt], h2, h3);
                    mma16816(acc[mt][np * 2],     ah[mt], l0, l1);   // hi*lo
                    mma16816(acc[mt][np * 2 + 1], ah[mt], l2, l3);
                    mma16816(acc[mt][np * 2],     al[mt], h0, h1);   // lo*hi
                    mma16816(acc[mt][np * 2 + 1], al[mt], h2, h3);
                }
            }
        }

        if (more) {
            char* nb = sm + (cur ^ 1) * STG_SZ;
            stA_smem(pa, nb, nb + MAT_SZ, t);
            stB_smem(pbh, nb + 2 * MAT_SZ, t);
            stB_smem(pbl, nb + 3 * MAT_SZ, t);
        }
        __syncthreads();
        cur ^= 1;
    }

    // epilogue: direct fp32 stores
    const int gid = lane >> 2, tig = lane & 3;
#pragma unroll
    for (int mt = 0; mt < 2; mt++) {
#pragma unroll
        for (int nt = 0; nt < 8; nt++) {
            int r = m0 + wm * 32 + mt * 16 + gid;
            int cc = n0 + wn * 64 + nt * 8 + tig * 2;
            *(float2*)(C + (size_t)r * DMODEL + cc) =
                make_float2(acc[mt][nt][0], acc[mt][nt][1]);
            *(float2*)(C + (size_t)(r + 8) * DMODEL + cc) =
                make_float2(acc[mt][nt][2], acc[mt][nt][3]);
        }
    }
}

__global__ __launch_bounds__(256, 1)
void gemm_qkv_mma(const float* __restrict__ X,
                  float* __restrict__ Q, float* __restrict__ K, float* __restrict__ V) {
    int bx = blockIdx.x;              // 24 = 3 matrices x 8 column tiles
    int sel = bx >> 3, bn = bx & 7;
    float* C = (sel == 0) ? Q : (sel == 1) ? K : V;
    gemm_mma_body(X, g_Wth[sel], g_Wtl[sel], C, blockIdx.y, bn);
}

__global__ __launch_bounds__(256, 1)
void gemm_o_mma(const float* __restrict__ Actx, float* __restrict__ Cout) {
    gemm_mma_body(Actx, g_Wth[3], g_Wtl[3], Cout, blockIdx.y, blockIdx.x);
}

// ---------------- flash-attention fp32 (FFMA2 inner loops) ----------------
__global__ __launch_bounds__(256)
void attn_kernel() {
    extern __shared__ float smf[];
    float* Qs = smf;                // [d][i], transposed, 64x68
    float* Ks = Qs + 64 * ATS;      // [d][j], transposed
    float* Vs = Ks + 64 * ATS;      // [j][c], row-major
    float* Ps = Vs + 64 * ATS;      // [i][j], row-major
    float* Bstrip = Ps + 64 * ATS;  // 127-entry bias strip

    const int t  = threadIdx.x;
    const int tx = t & 15, ty = t >> 4;
    const int i0 = ty << 2, j0 = tx << 2;
    const int qt = blockIdx.x;
    const int bh = blockIdx.y;
    const int b  = bh >> 4, h = bh & 15;
    const int q0 = qt << 6;

    const size_t qbase = (size_t)(b * SEQ + q0) * DMODEL + h * DK;
#pragma unroll
    for (int u = 0; u < 4; u++) {
        int e = t + u * 256;
        int i = e >> 4, d4 = (e & 15) << 2;
        float4 v = *(const float4*)(g_Q + qbase + (size_t)i * DMODEL + d4);
        Qs[(d4 + 0) * ATS + i] = v.x;
        Qs[(d4 + 1) * ATS + i] = v.y;
        Qs[(d4 + 2) * ATS + i] = v.z;
        Qs[(d4 + 3) * ATS + i] = v.w;
    }

    float m[4], l[4];
    ull o2[4][2];
#pragma unroll
    for (int r = 0; r < 4; r++) {
        m[r] = -1e30f; l[r] = 0.f;
        o2[r][0] = 0ULL; o2[r][1] = 0ULL;
    }

    for (int kt = 0; kt < SEQ / 64; kt++) {
        __syncthreads();
        const size_t kvbase = (size_t)(b * SEQ + (kt << 6)) * DMODEL + h * DK;
#pragma unroll
        for (int u = 0; u < 4; u++) {
            int e = t + u * 256;
            int j = e >> 4, c4 = (e & 15) << 2;
            float4 kv = *(const float4*)(g_K + kvbase + (size_t)j * DMODEL + c4);
            Ks[(c4 + 0) * ATS + j] = kv.x;
            Ks[(c4 + 1) * ATS + j] = kv.y;
            Ks[(c4 + 2) * ATS + j] = kv.z;
            Ks[(c4 + 3) * ATS + j] = kv.w;
            float4 vv = *(const float4*)(g_V + kvbase + (size_t)j * DMODEL + c4);
            *(float4*)(Vs + j * ATS + c4) = vv;
        }
        if (t < 127)
            Bstrip[t] = g_biasTab[h * 4096 + (kt << 6) - q0 - 63 + 2047 + t];
        __syncthreads();

        ull s2[4][2];
#pragma unroll
        for (int r = 0; r < 4; r++) { s2[r][0] = 0ULL; s2[r][1] = 0ULL; }
#pragma unroll 8
        for (int d = 0; d < 64; d++) {
            float4 qa = *(const float4*)(Qs + d * ATS + i0);
            ulonglong2 kb = *(const ulonglong2*)(Ks + d * ATS + j0);
            float qv[4] = {qa.x, qa.y, qa.z, qa.w};
#pragma unroll
            for (int r = 0; r < 4; r++) {
                ull aa = bcast2(qv[r]);
                ffma2(s2[r][0], aa, kb.x);
                ffma2(s2[r][1], aa, kb.y);
            }
        }
        float s[4][4];
#pragma unroll
        for (int r = 0; r < 4; r++) {
            float2 u0 = unpack2(s2[r][0]);
            float2 u1 = unpack2(s2[r][1]);
            s[r][0] = u0.x; s[r][1] = u0.y; s[r][2] = u1.x; s[r][3] = u1.y;
        }
#pragma unroll
        for (int r = 0; r < 4; r++)
#pragma unroll
            for (int c = 0; c < 4; c++)
                s[r][c] += Bstrip[(j0 + c) - (i0 + r) + 63];

#pragma unroll
        for (int r = 0; r < 4; r++) {
            float rm = fmaxf(fmaxf(s[r][0], s[r][1]), fmaxf(s[r][2], s[r][3]));
#pragma unroll
            for (int off = 8; off > 0; off >>= 1)
                rm = fmaxf(rm, __shfl_xor_sync(0xffffffffu, rm, off, 16));
            float mn = fmaxf(m[r], rm);
            float fr = __expf(m[r] - mn);
            m[r] = mn;
            float sum = 0.f;
#pragma unroll
            for (int c = 0; c < 4; c++) {
                s[r][c] = __expf(s[r][c] - mn);
                sum += s[r][c];
            }
#pragma unroll
            for (int off = 8; off > 0; off >>= 1)
                sum += __shfl_xor_sync(0xffffffffu, sum, off, 16);
            l[r] = l[r] * fr + sum;
            ull ff = bcast2(fr);
            mulf2(o2[r][0], ff);
            mulf2(o2[r][1], ff);
        }

#pragma unroll
        for (int r = 0; r < 4; r++)
            *(float4*)(Ps + (i0 + r) * ATS + j0) =
                make_float4(s[r][0], s[r][1], s[r][2], s[r][3]);
        __syncthreads();
#pragma unroll 2
        for (int j = 0; j < 64; j += 4) {
            float p[4][4];
#pragma unroll
            for (int r = 0; r < 4; r++) {
                float4 pv = *(const float4*)(Ps + (i0 + r) * ATS + j);
                p[r][0] = pv.x; p[r][1] = pv.y; p[r][2] = pv.z; p[r][3] = pv.w;
            }
#pragma unroll
            for (int jj = 0; jj < 4; jj++) {
                ulonglong2 vb = *(const ulonglong2*)(Vs + (j + jj) * ATS + j0);
#pragma unroll
                for (int r = 0; r < 4; r++) {
                    ull aa = bcast2(p[r][jj]);
                    ffma2(o2[r][0], aa, vb.x);
                    ffma2(o2[r][1], aa, vb.y);
                }
            }
        }
    }

#pragma unroll
    for (int r = 0; r < 4; r++) {
        float inv = 1.0f / l[r];
        float2 u0 = unpack2(o2[r][0]);
        float2 u1 = unpack2(o2[r][1]);
        float4 ov = make_float4(u0.x * inv, u0.y * inv, u1.x * inv, u1.y * inv);
        *(float4*)(g_ctx + (size_t)(b * SEQ + q0 + i0 + r) * DMODEL + h * DK + j0) = ov;
    }
}

// ---------------- launch ----------------
extern "C" void kernel_launch(void* const* d_in, const int* in_sizes, int n_in,
                              void* d_out, int out_size) {
    const float* X   = (const float*)d_in[0];
    const float* Wq  = (const float*)d_in[1];
    const float* Wk  = (const float*)d_in[2];
    const float* Wv  = (const float*)d_in[3];
    const float* Wo  = (const float*)d_in[4];
    const float* rbi = (const float*)d_in[5];
    float* out = (float*)d_out;

    float *pQ, *pK, *pV, *pC;
    cudaGetSymbolAddress((void**)&pQ, g_Q);
    cudaGetSymbolAddress((void**)&pK, g_K);
    cudaGetSymbolAddress((void**)&pV, g_V);
    cudaGetSymbolAddress((void**)&pC, g_ctx);

    cudaFuncSetAttribute(attn_kernel, cudaFuncAttributeMaxDynamicSharedMemorySize,
                         ATTN_SMEM);
    cudaFuncSetAttribute(gemm_qkv_mma, cudaFuncAttributeMaxDynamicSharedMemorySize,
                         GEMM_SMEM);
    cudaFuncSetAttribute(gemm_o_mma, cudaFuncAttributeMaxDynamicSharedMemorySize,
                         GEMM_SMEM);

    bias_table_kernel<<<(HEADS * 4095 + 255) / 256, 256>>>(rbi);
    wconv_kernel<<<dim3(32, 32, 4), dim3(32, 8)>>>(Wq, Wk, Wv, Wo);

    gemm_qkv_mma<<<dim3(24, MROWS / 128), 256, GEMM_SMEM>>>(X, pQ, pK, pV);

    attn_kernel<<<dim3(SEQ / 64, BATCH * HEADS), 256, ATTN_SMEM>>>();

    gemm_o_mma<<<dim3(DMODEL / 128, MROWS / 128), 256, GEMM_SMEM>>>(pC, out);
}

// round 12
// speedup vs baseline: 1.5797x; 1.5797x over previous
#include <cuda_runtime.h>
#include <cuda_bf16.h>
#include <math.h>

#define BATCH   2
#define SEQ     2048
#define DMODEL  1024
#define HEADS   16
#define DK      64
#define MROWS   (BATCH * SEQ)      // 4096
#define ATS     68                 // attention smem row stride (floats)
#define ATTN_SMEM ((4 * 64 * ATS + 128) * 4)   // 70144 bytes

typedef unsigned long long ull;
typedef unsigned int u32;

// ---------------- packed f32x2 helpers (attention path) ----------------
__device__ __forceinline__ void ffma2(ull& d, ull a, ull b) {
    asm("fma.rn.f32x2 %0, %1, %2, %0;" : "+l"(d) : "l"(a), "l"(b));
}
__device__ __forceinline__ ull bcast2(float a) {
    ull r; asm("mov.b64 %0, {%1, %1};" : "=l"(r) : "f"(a)); return r;
}
__device__ __forceinline__ void mulf2(ull& d, ull a) {
    asm("mul.rn.f32x2 %0, %0, %1;" : "+l"(d) : "l"(a));
}
__device__ __forceinline__ float2 unpack2(ull v) {
    float2 f; asm("mov.b64 {%0, %1}, %2;" : "=f"(f.x), "=f"(f.y) : "l"(v)); return f;
}

// ---------------- warp-MMA helpers (baseline PTX, works on compute_103) ----
__device__ __forceinline__ u32 smem_u32(const void* p) {
    u32 a;
    asm("{ .reg .u64 t; cvta.to.shared.u64 t, %1; cvt.u32.u64 %0, t; }"
        : "=r"(a) : "l"(p));
    return a;
}
__device__ __forceinline__ void ldsm4(u32& r0, u32& r1, u32& r2, u32& r3, u32 addr) {
    asm volatile("ldmatrix.sync.aligned.m8n8.x4.shared.b16 {%0,%1,%2,%3}, [%4];"
                 : "=r"(r0), "=r"(r1), "=r"(r2), "=r"(r3) : "r"(addr));
}
__device__ __forceinline__ void mma16816(float* c, const u32* a, u32 b0, u32 b1) {
    asm volatile("mma.sync.aligned.m16n8k16.row.col.f32.bf16.bf16.f32 "
                 "{%0,%1,%2,%3}, {%4,%5,%6,%7}, {%8,%9}, {%0,%1,%2,%3};"
                 : "+f"(c[0]), "+f"(c[1]), "+f"(c[2]), "+f"(c[3])
                 : "r"(a[0]), "r"(a[1]), "r"(a[2]), "r"(a[3]), "r"(b0), "r"(b1));
}
__device__ __forceinline__ void cp16(u32 dst, const void* src) {
    asm volatile("cp.async.cg.shared.global [%0], [%1], 16;"
                 :: "r"(dst), "l"(__cvta_generic_to_global(src)));
}

// ---------------- scratch (device globals: allocation-free) ----------------
__device__ float g_Q[MROWS * DMODEL];
__device__ float g_K[MROWS * DMODEL];
__device__ float g_V[MROWS * DMODEL];
__device__ float g_biasTab[HEADS * 4096];                 // [h][rp + 2047]
__device__ __nv_bfloat16 g_Xhi[MROWS * DMODEL];           // X hi/lo split
__device__ __nv_bfloat16 g_Xlo[MROWS * DMODEL];
__device__ __nv_bfloat16 g_Chi[MROWS * DMODEL];           // ctx hi/lo split
__device__ __nv_bfloat16 g_Clo[MROWS * DMODEL];
__device__ __nv_bfloat16 g_Wth[4][DMODEL * DMODEL];       // W^T hi, [n][k]
__device__ __nv_bfloat16 g_Wtl[4][DMODEL * DMODEL];       // W^T lo, [n][k]

// ---------------- T5 relative-position bias table ----------------
__global__ void bias_table_kernel(const float* __restrict__ rel_bias) {
    int idx = blockIdx.x * blockDim.x + threadIdx.x;
    if (idx >= HEADS * 4095) return;
    int h  = idx / 4095;
    int i  = idx % 4095;
    int rp = i - 2047;
    int rb  = (rp > 0) ? 16 : 0;
    int rpa = rp < 0 ? -rp : rp;
    int bkt;
    if (rpa < 8) {
        bkt = rpa;
    } else {
        float t = logf((float)rpa * 0.125f);
        t = t / 2.7725887222397812f;
        t = t * 8.0f;
        bkt = 8 + (int)t;
        if (bkt > 15) bkt = 15;
    }
    g_biasTab[h * 4096 + i] = rel_bias[(rb + bkt) * HEADS + h];
}

// ---------------- weight transpose + bf16 hi/lo split prepass ----------------
__global__ void wconv_kernel(const float* __restrict__ Wq, const float* __restrict__ Wk,
                             const float* __restrict__ Wv, const float* __restrict__ Wo) {
    __shared__ float tile[32][33];
    int z = blockIdx.z;
    const float* W = (z == 0) ? Wq : (z == 1) ? Wk : (z == 2) ? Wv : Wo;
    __nv_bfloat16* Oh = g_Wth[z];
    __nv_bfloat16* Ol = g_Wtl[z];
    int x0 = blockIdx.x * 32, y0 = blockIdx.y * 32;
    int tx = threadIdx.x, ty = threadIdx.y;
#pragma unroll
    for (int i = 0; i < 4; i++)
        tile[ty + i * 8][tx] = W[(size_t)(y0 + ty + i * 8) * DMODEL + x0 + tx];
    __syncthreads();
#pragma unroll
    for (int i = 0; i < 4; i++) {
        float v = tile[tx][ty + i * 8];
        int n = x0 + ty + i * 8, k = y0 + tx;
        __nv_bfloat16 h = __float2bfloat16(v);
        float lo = v - __bfloat162float(h);
        Oh[(size_t)n * DMODEL + k] = h;
        Ol[(size_t)n * DMODEL + k] = __float2bfloat16(lo);
    }
}

// ---------------- X hi/lo split prepass ----------------
__global__ void xsplit_kernel(const float* __restrict__ X) {
    int i = (blockIdx.x * 256 + threadIdx.x) * 4;
    float4 v = *(const float4*)(X + i);
    __nv_bfloat162 h0 = __floats2bfloat162_rn(v.x, v.y);
    __nv_bfloat162 h1 = __floats2bfloat162_rn(v.z, v.w);
    float2 f0 = __bfloat1622float2(h0);
    float2 f1 = __bfloat1622float2(h1);
    __nv_bfloat162 l0 = __floats2bfloat162_rn(v.x - f0.x, v.y - f0.y);
    __nv_bfloat162 l1 = __floats2bfloat162_rn(v.z - f1.x, v.w - f1.y);
    *(__nv_bfloat162*)(g_Xhi + i)     = h0;
    *(__nv_bfloat162*)(g_Xhi + i + 2) = h1;
    *(__nv_bfloat162*)(g_Xlo + i)     = l0;
    *(__nv_bfloat162*)(g_Xlo + i + 2) = l1;
}

// ---------------- MMA GEMM: C = A @ W (3-pass bf16, cp.async 3-stage) ------
// smem per stage: Ah, Al, Bh, Bl each [128 rows][80B stride] (conflict-free
// for ldmatrix: 8 rows x 80B land on 8 disjoint 16B bank groups)
#define RSB     80
#define MAT_SZ  (128 * RSB)              // 10240
#define STG_SZ  (4 * MAT_SZ)             // 40960
#define NSTG    3
#define GEMM_SMEM (NSTG * STG_SZ)        // 122880
#define NCHUNK  (DMODEL / 32)            // 32

__device__ __forceinline__ void cp_chunk(
    u32 stg,
    const __nv_bfloat16* __restrict__ Ah, const __nv_bfloat16* __restrict__ Al,
    const __nv_bfloat16* __restrict__ Bh, const __nv_bfloat16* __restrict__ Bl,
    int t, int k0)
{
    // 4 matrices x 512 16B-copies; u>>1 selects matrix (compile-time per iter)
#pragma unroll
    for (int u = 0; u < 8; u++) {
        const int id = t + (u & 1) * 256;        // 0..511
        const int row = id >> 2, kq = id & 3;
        const __nv_bfloat16* src =
            (u < 2 ? Ah : u < 4 ? Al : u < 6 ? Bh : Bl)
            + (size_t)row * DMODEL + k0 + kq * 8;
        cp16(stg + (u >> 1) * MAT_SZ + row * RSB + kq * 16, src);
    }
}

__device__ __forceinline__ void gemm_mma_body(
    const __nv_bfloat16* __restrict__ Ah_g, const __nv_bfloat16* __restrict__ Al_g,
    const __nv_bfloat16* __restrict__ Bh_g, const __nv_bfloat16* __restrict__ Bl_g,
    float* __restrict__ C, int bm, int bn)
{
    extern __shared__ char sm[];
    const u32 sb = smem_u32(sm);
    const int t = threadIdx.x, wid = t >> 5, lane = t & 31;
    const int wm = wid >> 1, wn = wid & 1;        // 4x2 warp grid
    const int m0 = bm * 128, n0 = bn * 128;

    const __nv_bfloat16* Ah = Ah_g + (size_t)m0 * DMODEL;
    const __nv_bfloat16* Al = Al_g + (size_t)m0 * DMODEL;
    const __nv_bfloat16* Bh = Bh_g + (size_t)n0 * DMODEL;
    const __nv_bfloat16* Bl = Bl_g + (size_t)n0 * DMODEL;

    float acc[2][8][4];
#pragma unroll
    for (int i = 0; i < 2; i++)
#pragma unroll
        for (int j = 0; j < 8; j++)
#pragma unroll
            for (int q = 0; q < 4; q++) acc[i][j][q] = 0.f;

    // lane decomposition for ldmatrix addressing
    const int r15 = lane & 15, kh = lane >> 4;                 // A tiles
    const int bn_lane = ((lane >> 4) << 3) + (lane & 7);       // B tiles
    const int bkh = (lane >> 3) & 1;

    // prologue: fill all 3 stages
    cp_chunk(sb,              Ah, Al, Bh, Bl, t, 0);
    asm volatile("cp.async.commit_group;" ::: "memory");
    cp_chunk(sb + STG_SZ,     Ah, Al, Bh, Bl, t, 32);
    asm volatile("cp.async.commit_group;" ::: "memory");
    cp_chunk(sb + 2 * STG_SZ, Ah, Al, Bh, Bl, t, 64);
    asm volatile("cp.async.commit_group;" ::: "memory");

#pragma unroll 1
    for (int c = 0; c < NCHUNK; c++) {
        if (c < NCHUNK - 2)      asm volatile("cp.async.wait_group 2;" ::: "memory");
        else if (c == NCHUNK - 2) asm volatile("cp.async.wait_group 1;" ::: "memory");
        else                      asm volatile("cp.async.wait_group 0;" ::: "memory");
        __syncthreads();

        const u32 stg = sb + (c % NSTG) * STG_SZ;
        const u32 a_h = stg, a_l = stg + MAT_SZ;
        const u32 b_h = stg + 2 * MAT_SZ, b_l = stg + 3 * MAT_SZ;

#pragma unroll
        for (int ks = 0; ks < 2; ks++) {
            const u32 kofA = (u32)((ks * 16 + kh * 8) * 2);
            const u32 kofB = (u32)((ks * 16 + bkh * 8) * 2);
            u32 ah[2][4], al[2][4];
#pragma unroll
            for (int mt = 0; mt < 2; mt++) {
                u32 ar = (u32)((wm * 32 + mt * 16 + r15) * RSB);
                ldsm4(ah[mt][0], ah[mt][1], ah[mt][2], ah[mt][3], a_h + ar + kofA);
                ldsm4(al[mt][0], al[mt][1], al[mt][2], al[mt][3], a_l + ar + kofA);
            }
#pragma unroll
            for (int np = 0; np < 4; np++) {         // each covers 16 n cols
                u32 br = (u32)((wn * 64 + np * 16 + bn_lane) * RSB);
                u32 h0, h1, h2, h3, l0, l1, l2, l3;
                ldsm4(h0, h1, h2, h3, b_h + br + kofB);
                ldsm4(l0, l1, l2, l3, b_l + br + kofB);
#pragma unroll
                for (int mt = 0; mt < 2; mt++) {
                    mma16816(acc[mt][np * 2],     ah[mt], h0, h1);   // hi*hi
                    mma16816(acc[mt][np * 2 + 1], ah[mt], h2, h3);
                    mma16816(acc[mt][np * 2],     ah[mt], l0, l1);   // hi*lo
                    mma16816(acc[mt][np * 2 + 1], ah[mt], l2, l3);
                    mma16816(acc[mt][np * 2],     al[mt], h0, h1);   // lo*hi
                    mma16816(acc[mt][np * 2 + 1], al[mt], h2, h3);
                }
            }
        }

        __syncthreads();                 // all warps done reading this stage
        if (c + NSTG < NCHUNK) {
            cp_chunk(stg, Ah, Al, Bh, Bl, t, (c + NSTG) * 32);
            asm volatile("cp.async.commit_group;" ::: "memory");
        }
    }

    // epilogue: direct fp32 stores
    const int gid = lane >> 2, tig = lane & 3;
#pragma unroll
    for (int mt = 0; mt < 2; mt++) {
#pragma unroll
        for (int nt = 0; nt < 8; nt++) {
            int r = m0 + wm * 32 + mt * 16 + gid;
            int cc = n0 + wn * 64 + nt * 8 + tig * 2;
            *(float2*)(C + (size_t)r * DMODEL + cc) =
                make_float2(acc[mt][nt][0], acc[mt][nt][1]);
            *(float2*)(C + (size_t)(r + 8) * DMODEL + cc) =
                make_float2(acc[mt][nt][2], acc[mt][nt][3]);
        }
    }
}

__global__ __launch_bounds__(256, 1)
void gemm_qkv_mma(float* __restrict__ Q, float* __restrict__ K, float* __restrict__ V) {
    int bx = blockIdx.x;              // 24 = 3 matrices x 8 column tiles
    int sel = bx >> 3, bn = bx & 7;
    float* C = (sel == 0) ? Q : (sel == 1) ? K : V;
    gemm_mma_body(g_Xhi, g_Xlo, g_Wth[sel], g_Wtl[sel], C, blockIdx.y, bn);
}

__global__ __launch_bounds__(256, 1)
void gemm_o_mma(float* __restrict__ Cout) {
    gemm_mma_body(g_Chi, g_Clo, g_Wth[3], g_Wtl[3], Cout, blockIdx.y, blockIdx.x);
}

// ---------------- flash-attention fp32 (FFMA2 inner loops) ----------------
__global__ __launch_bounds__(256)
void attn_kernel() {
    extern __shared__ float smf[];
    float* Qs = smf;                // [d][i], transposed, 64x68
    float* Ks = Qs + 64 * ATS;      // [d][j], transposed
    float* Vs = Ks + 64 * ATS;      // [j][c], row-major
    float* Ps = Vs + 64 * ATS;      // [i][j], row-major
    float* Bstrip = Ps + 64 * ATS;  // 127-entry bias strip

    const int t  = threadIdx.x;
    const int tx = t & 15, ty = t >> 4;
    const int i0 = ty << 2, j0 = tx << 2;
    const int qt = blockIdx.x;
    const int bh = blockIdx.y;
    const int b  = bh >> 4, h = bh & 15;
    const int q0 = qt << 6;

    const size_t qbase = (size_t)(b * SEQ + q0) * DMODEL + h * DK;
#pragma unroll
    for (int u = 0; u < 4; u++) {
        int e = t + u * 256;
        int i = e >> 4, d4 = (e & 15) << 2;
        float4 v = *(const float4*)(g_Q + qbase + (size_t)i * DMODEL + d4);
        Qs[(d4 + 0) * ATS + i] = v.x;
        Qs[(d4 + 1) * ATS + i] = v.y;
        Qs[(d4 + 2) * ATS + i] = v.z;
        Qs[(d4 + 3) * ATS + i] = v.w;
    }

    float m[4], l[4];
    ull o2[4][2];
#pragma unroll
    for (int r = 0; r < 4; r++) {
        m[r] = -1e30f; l[r] = 0.f;
        o2[r][0] = 0ULL; o2[r][1] = 0ULL;
    }

    for (int kt = 0; kt < SEQ / 64; kt++) {
        __syncthreads();
        const size_t kvbase = (size_t)(b * SEQ + (kt << 6)) * DMODEL + h * DK;
#pragma unroll
        for (int u = 0; u < 4; u++) {
            int e = t + u * 256;
            int j = e >> 4, c4 = (e & 15) << 2;
            float4 kv = *(const float4*)(g_K + kvbase + (size_t)j * DMODEL + c4);
            Ks[(c4 + 0) * ATS + j] = kv.x;
            Ks[(c4 + 1) * ATS + j] = kv.y;
            Ks[(c4 + 2) * ATS + j] = kv.z;
            Ks[(c4 + 3) * ATS + j] = kv.w;
            float4 vv = *(const float4*)(g_V + kvbase + (size_t)j * DMODEL + c4);
            *(float4*)(Vs + j * ATS + c4) = vv;
        }
        if (t < 127)
            Bstrip[t] = g_biasTab[h * 4096 + (kt << 6) - q0 - 63 + 2047 + t];
        __syncthreads();

        ull s2[4][2];
#pragma unroll
        for (int r = 0; r < 4; r++) { s2[r][0] = 0ULL; s2[r][1] = 0ULL; }
#pragma unroll 8
        for (int d = 0; d < 64; d++) {
            float4 qa = *(const float4*)(Qs + d * ATS + i0);
            ulonglong2 kb = *(const ulonglong2*)(Ks + d * ATS + j0);
            float qv[4] = {qa.x, qa.y, qa.z, qa.w};
#pragma unroll
            for (int r = 0; r < 4; r++) {
                ull aa = bcast2(qv[r]);
                ffma2(s2[r][0], aa, kb.x);
                ffma2(s2[r][1], aa, kb.y);
            }
        }
        float s[4][4];
#pragma unroll
        for (int r = 0; r < 4; r++) {
            float2 u0 = unpack2(s2[r][0]);
            float2 u1 = unpack2(s2[r][1]);
            s[r][0] = u0.x; s[r][1] = u0.y; s[r][2] = u1.x; s[r][3] = u1.y;
        }
#pragma unroll
        for (int r = 0; r < 4; r++)
#pragma unroll
            for (int c = 0; c < 4; c++)
                s[r][c] += Bstrip[(j0 + c) - (i0 + r) + 63];

#pragma unroll
        for (int r = 0; r < 4; r++) {
            float rm = fmaxf(fmaxf(s[r][0], s[r][1]), fmaxf(s[r][2], s[r][3]));
#pragma unroll
            for (int off = 8; off > 0; off >>= 1)
                rm = fmaxf(rm, __shfl_xor_sync(0xffffffffu, rm, off, 16));
            float mn = fmaxf(m[r], rm);
            float fr = __expf(m[r] - mn);
            m[r] = mn;
            float sum = 0.f;
#pragma unroll
            for (int c = 0; c < 4; c++) {
                s[r][c] = __expf(s[r][c] - mn);
                sum += s[r][c];
            }
#pragma unroll
            for (int off = 8; off > 0; off >>= 1)
                sum += __shfl_xor_sync(0xffffffffu, sum, off, 16);
            l[r] = l[r] * fr + sum;
            ull ff = bcast2(fr);
            mulf2(o2[r][0], ff);
            mulf2(o2[r][1], ff);
        }

#pragma unroll
        for (int r = 0; r < 4; r++)
            *(float4*)(Ps + (i0 + r) * ATS + j0) =
                make_float4(s[r][0], s[r][1], s[r][2], s[r][3]);
        __syncthreads();
#pragma unroll 2
        for (int j = 0; j < 64; j += 4) {
            float p[4][4];
#pragma unroll
            for (int r = 0; r < 4; r++) {
                float4 pv = *(const float4*)(Ps + (i0 + r) * ATS + j);
                p[r][0] = pv.x; p[r][1] = pv.y; p[r][2] = pv.z; p[r][3] = pv.w;
            }
#pragma unroll
            for (int jj = 0; jj < 4; jj++) {
                ulonglong2 vb = *(const ulonglong2*)(Vs + (j + jj) * ATS + j0);
#pragma unroll
                for (int r = 0; r < 4; r++) {
                    ull aa = bcast2(p[r][jj]);
                    ffma2(o2[r][0], aa, vb.x);
                    ffma2(o2[r][1], aa, vb.y);
                }
            }
        }
    }

    // ctx stored directly as bf16 hi/lo split (feeds the O projection MMA)
#pragma unroll
    for (int r = 0; r < 4; r++) {
        float inv = 1.0f / l[r];
        float2 u0 = unpack2(o2[r][0]);
        float2 u1 = unpack2(o2[r][1]);
        float v0 = u0.x * inv, v1 = u0.y * inv, v2 = u1.x * inv, v3 = u1.y * inv;
        __nv_bfloat162 h0 = __floats2bfloat162_rn(v0, v1);
        __nv_bfloat162 h1 = __floats2bfloat162_rn(v2, v3);
        float2 f0 = __bfloat1622float2(h0);
        float2 f1 = __bfloat1622float2(h1);
        __nv_bfloat162 lo0 = __floats2bfloat162_rn(v0 - f0.x, v1 - f0.y);
        __nv_bfloat162 lo1 = __floats2bfloat162_rn(v2 - f1.x, v3 - f1.y);
        size_t off = (size_t)(b * SEQ + q0 + i0 + r) * DMODEL + h * DK + j0;
        *(__nv_bfloat162*)(g_Chi + off)     = h0;
        *(__nv_bfloat162*)(g_Chi + off + 2) = h1;
        *(__nv_bfloat162*)(g_Clo + off)     = lo0;
        *(__nv_bfloat162*)(g_Clo + off + 2) = lo1;
    }
}

// ---------------- launch ----------------
extern "C" void kernel_launch(void* const* d_in, const int* in_sizes, int n_in,
                              void* d_out, int out_size) {
    const float* X   = (const float*)d_in[0];
    const float* Wq  = (const float*)d_in[1];
    const float* Wk  = (const float*)d_in[2];
    const float* Wv  = (const float*)d_in[3];
    const float* Wo  = (const float*)d_in[4];
    const float* rbi = (const float*)d_in[5];
    float* out = (float*)d_out;

    float *pQ, *pK, *pV;
    cudaGetSymbolAddress((void**)&pQ, g_Q);
    cudaGetSymbolAddress((void**)&pK, g_K);
    cudaGetSymbolAddress((void**)&pV, g_V);

    cudaFuncSetAttribute(attn_kernel, cudaFuncAttributeMaxDynamicSharedMemorySize,
                         ATTN_SMEM);
    cudaFuncSetAttribute(gemm_qkv_mma, cudaFuncAttributeMaxDynamicSharedMemorySize,
                         GEMM_SMEM);
    cudaFuncSetAttribute(gemm_o_mma, cudaFuncAttributeMaxDynamicSharedMemorySize,
                         GEMM_SMEM);

    bias_table_kernel<<<(HEADS * 4095 + 255) / 256, 256>>>(rbi);
    wconv_kernel<<<dim3(32, 32, 4), dim3(32, 8)>>>(Wq, Wk, Wv, Wo);
    xsplit_kernel<<<MROWS * DMODEL / 1024, 256>>>(X);

    gemm_qkv_mma<<<dim3(24, MROWS / 128), 256, GEMM_SMEM>>>(pQ, pK, pV);

    attn_kernel<<<dim3(SEQ / 64, BATCH * HEADS), 256, ATTN_SMEM>>>();

    gemm_o_mma<<<dim3(DMODEL / 128, MROWS / 128), 256, GEMM_SMEM>>>(out);
}

// round 14
// speedup vs baseline: 2.9362x; 1.8587x over previous
#include <cuda_runtime.h>
#include <cuda_bf16.h>
#include <math.h>

#define BATCH   2
#define SEQ     2048
#define DMODEL  1024
#define HEADS   16
#define DK      64
#define MROWS   (BATCH * SEQ)      // 4096

typedef unsigned long long ull;
typedef unsigned int u32;

// ---------------- warp-MMA helpers (baseline PTX, works on compute_103) ----
__device__ __forceinline__ u32 smem_u32(const void* p) {
    u32 a;
    asm("{ .reg .u64 t; cvta.to.shared.u64 t, %1; cvt.u32.u64 %0, t; }"
        : "=r"(a) : "l"(p));
    return a;
}
__device__ __forceinline__ void ldsm4(u32& r0, u32& r1, u32& r2, u32& r3, u32 addr) {
    asm volatile("ldmatrix.sync.aligned.m8n8.x4.shared.b16 {%0,%1,%2,%3}, [%4];"
                 : "=r"(r0), "=r"(r1), "=r"(r2), "=r"(r3) : "r"(addr));
}
__device__ __forceinline__ void ldsm4t(u32& r0, u32& r1, u32& r2, u32& r3, u32 addr) {
    asm volatile("ldmatrix.sync.aligned.m8n8.x4.trans.shared.b16 {%0,%1,%2,%3}, [%4];"
                 : "=r"(r0), "=r"(r1), "=r"(r2), "=r"(r3) : "r"(addr));
}
__device__ __forceinline__ void mma16816(float* c, const u32* a, u32 b0, u32 b1) {
    asm volatile("mma.sync.aligned.m16n8k16.row.col.f32.bf16.bf16.f32 "
                 "{%0,%1,%2,%3}, {%4,%5,%6,%7}, {%8,%9}, {%0,%1,%2,%3};"
                 : "+f"(c[0]), "+f"(c[1]), "+f"(c[2]), "+f"(c[3])
                 : "r"(a[0]), "r"(a[1]), "r"(a[2]), "r"(a[3]), "r"(b0), "r"(b1));
}
__device__ __forceinline__ void cp16(u32 dst, const void* src) {
    asm volatile("cp.async.cg.shared.global [%0], [%1], 16;"
                 :: "r"(dst), "l"(__cvta_generic_to_global(src)));
}
// pack two f32 -> bf16x2 (lo half = first arg)
__device__ __forceinline__ u32 pk2(float lo, float hi) {
    u32 d; asm("cvt.rn.bf16x2.f32 %0, %1, %2;" : "=r"(d) : "f"(hi), "f"(lo));
    return d;
}
__device__ __forceinline__ void hilo_store(__nv_bfloat16* Ch, __nv_bfloat16* Cl,
                                           size_t off, float v0, float v1) {
    u32 hi = pk2(v0, v1);
    float f0 = __uint_as_float(hi << 16);
    float f1 = __uint_as_float(hi & 0xffff0000u);
    u32 lo = pk2(v0 - f0, v1 - f1);
    *(u32*)(Ch + off) = hi;
    *(u32*)(Cl + off) = lo;
}

// ---------------- scratch (device globals: allocation-free) ----------------
__device__ float g_biasTab[HEADS * 4096];                 // [h][rp + 2047]
__device__ __nv_bfloat16 g_Xhi[MROWS * DMODEL];
__device__ __nv_bfloat16 g_Xlo[MROWS * DMODEL];
__device__ __nv_bfloat16 g_Qh[MROWS * DMODEL];
__device__ __nv_bfloat16 g_Ql[MROWS * DMODEL];
__device__ __nv_bfloat16 g_Kh[MROWS * DMODEL];
__device__ __nv_bfloat16 g_Kl[MROWS * DMODEL];
__device__ __nv_bfloat16 g_Vh[MROWS * DMODEL];
__device__ __nv_bfloat16 g_Vl[MROWS * DMODEL];
__device__ __nv_bfloat16 g_Chi[MROWS * DMODEL];           // ctx hi/lo
__device__ __nv_bfloat16 g_Clo[MROWS * DMODEL];
__device__ __nv_bfloat16 g_Wth[4][DMODEL * DMODEL];       // W^T hi, [n][k]
__device__ __nv_bfloat16 g_Wtl[4][DMODEL * DMODEL];       // W^T lo, [n][k]

// ---------------- T5 relative-position bias table ----------------
__global__ void bias_table_kernel(const float* __restrict__ rel_bias) {
    int idx = blockIdx.x * blockDim.x + threadIdx.x;
    if (idx >= HEADS * 4095) return;
    int h  = idx / 4095;
    int i  = idx % 4095;
    int rp = i - 2047;
    int rb  = (rp > 0) ? 16 : 0;
    int rpa = rp < 0 ? -rp : rp;
    int bkt;
    if (rpa < 8) {
        bkt = rpa;
    } else {
        float t = logf((float)rpa * 0.125f);
        t = t / 2.7725887222397812f;
        t = t * 8.0f;
        bkt = 8 + (int)t;
        if (bkt > 15) bkt = 15;
    }
    g_biasTab[h * 4096 + i] = rel_bias[(rb + bkt) * HEADS + h];
}

// ---------------- weight transpose + bf16 hi/lo split prepass ----------------
__global__ void wconv_kernel(const float* __restrict__ Wq, const float* __restrict__ Wk,
                             const float* __restrict__ Wv, const float* __restrict__ Wo) {
    __shared__ float tile[32][33];
    int z = blockIdx.z;
    const float* W = (z == 0) ? Wq : (z == 1) ? Wk : (z == 2) ? Wv : Wo;
    __nv_bfloat16* Oh = g_Wth[z];
    __nv_bfloat16* Ol = g_Wtl[z];
    int x0 = blockIdx.x * 32, y0 = blockIdx.y * 32;
    int tx = threadIdx.x, ty = threadIdx.y;
#pragma unroll
    for (int i = 0; i < 4; i++)
        tile[ty + i * 8][tx] = W[(size_t)(y0 + ty + i * 8) * DMODEL + x0 + tx];
    __syncthreads();
#pragma unroll
    for (int i = 0; i < 4; i++) {
        float v = tile[tx][ty + i * 8];
        int n = x0 + ty + i * 8, k = y0 + tx;
        __nv_bfloat16 h = __float2bfloat16(v);
        float lo = v - __bfloat162float(h);
        Oh[(size_t)n * DMODEL + k] = h;
        Ol[(size_t)n * DMODEL + k] = __float2bfloat16(lo);
    }
}

// ---------------- X hi/lo split prepass ----------------
__global__ void xsplit_kernel(const float* __restrict__ X) {
    int i = (blockIdx.x * 256 + threadIdx.x) * 4;
    float4 v = *(const float4*)(X + i);
    __nv_bfloat162 h0 = __floats2bfloat162_rn(v.x, v.y);
    __nv_bfloat162 h1 = __floats2bfloat162_rn(v.z, v.w);
    float2 f0 = __bfloat1622float2(h0);
    float2 f1 = __bfloat1622float2(h1);
    __nv_bfloat162 l0 = __floats2bfloat162_rn(v.x - f0.x, v.y - f0.y);
    __nv_bfloat162 l1 = __floats2bfloat162_rn(v.z - f1.x, v.w - f1.y);
    *(__nv_bfloat162*)(g_Xhi + i)     = h0;
    *(__nv_bfloat162*)(g_Xhi + i + 2) = h1;
    *(__nv_bfloat162*)(g_Xlo + i)     = l0;
    *(__nv_bfloat162*)(g_Xlo + i + 2) = l1;
}

// ---------------- MMA GEMM: C = A @ W (3-pass bf16, cp.async 3-stage) ------
#define RSB     80
#define MAT_SZ  (128 * RSB)              // 10240
#define STG_SZ  (4 * MAT_SZ)             // 40960
#define NSTG    3
#define GEMM_SMEM (NSTG * STG_SZ)        // 122880
#define NCHUNK  (DMODEL / 32)            // 32

__device__ __forceinline__ void cp_chunk(
    u32 stg,
    const __nv_bfloat16* __restrict__ Ah, const __nv_bfloat16* __restrict__ Al,
    const __nv_bfloat16* __restrict__ Bh, const __nv_bfloat16* __restrict__ Bl,
    int t, int k0)
{
#pragma unroll
    for (int u = 0; u < 8; u++) {
        const int id = t + (u & 1) * 256;        // 0..511
        const int row = id >> 2, kq = id & 3;
        const __nv_bfloat16* src =
            (u < 2 ? Ah : u < 4 ? Al : u < 6 ? Bh : Bl)
            + (size_t)row * DMODEL + k0 + kq * 8;
        cp16(stg + (u >> 1) * MAT_SZ + row * RSB + kq * 16, src);
    }
}

// MODE 0: f32 output to Cf.  MODE 1: bf16 hi/lo output to Ch/Cl.
template<int MODE>
__device__ __forceinline__ void gemm_mma_body(
    const __nv_bfloat16* __restrict__ Ah_g, const __nv_bfloat16* __restrict__ Al_g,
    const __nv_bfloat16* __restrict__ Bh_g, const __nv_bfloat16* __restrict__ Bl_g,
    float* __restrict__ Cf, __nv_bfloat16* __restrict__ Ch,
    __nv_bfloat16* __restrict__ Cl, int bm, int bn)
{
    extern __shared__ char sm[];
    const u32 sb = smem_u32(sm);
    const int t = threadIdx.x, wid = t >> 5, lane = t & 31;
    const int wm = wid >> 1, wn = wid & 1;        // 4x2 warp grid
    const int m0 = bm * 128, n0 = bn * 128;

    const __nv_bfloat16* Ah = Ah_g + (size_t)m0 * DMODEL;
    const __nv_bfloat16* Al = Al_g + (size_t)m0 * DMODEL;
    const __nv_bfloat16* Bh = Bh_g + (size_t)n0 * DMODEL;
    const __nv_bfloat16* Bl = Bl_g + (size_t)n0 * DMODEL;

    float acc[2][8][4];
#pragma unroll
    for (int i = 0; i < 2; i++)
#pragma unroll
        for (int j = 0; j < 8; j++)
#pragma unroll
            for (int q = 0; q < 4; q++) acc[i][j][q] = 0.f;

    const int r15 = lane & 15, kh = lane >> 4;
    const int bn_lane = ((lane >> 4) << 3) + (lane & 7);
    const int bkh = (lane >> 3) & 1;

    cp_chunk(sb,              Ah, Al, Bh, Bl, t, 0);
    asm volatile("cp.async.commit_group;" ::: "memory");
    cp_chunk(sb + STG_SZ,     Ah, Al, Bh, Bl, t, 32);
    asm volatile("cp.async.commit_group;" ::: "memory");
    cp_chunk(sb + 2 * STG_SZ, Ah, Al, Bh, Bl, t, 64);
    asm volatile("cp.async.commit_group;" ::: "memory");

#pragma unroll 1
    for (int c = 0; c < NCHUNK; c++) {
        if (c < NCHUNK - 2)      asm volatile("cp.async.wait_group 2;" ::: "memory");
        else if (c == NCHUNK - 2) asm volatile("cp.async.wait_group 1;" ::: "memory");
        else                      asm volatile("cp.async.wait_group 0;" ::: "memory");
        __syncthreads();

        const u32 stg = sb + (c % NSTG) * STG_SZ;
        const u32 a_h = stg, a_l = stg + MAT_SZ;
        const u32 b_h = stg + 2 * MAT_SZ, b_l = stg + 3 * MAT_SZ;

#pragma unroll
        for (int ks = 0; ks < 2; ks++) {
            const u32 kofA = (u32)((ks * 16 + kh * 8) * 2);
            const u32 kofB = (u32)((ks * 16 + bkh * 8) * 2);
            u32 ah[2][4], al[2][4];
#pragma unroll
            for (int mt = 0; mt < 2; mt++) {
                u32 ar = (u32)((wm * 32 + mt * 16 + r15) * RSB);
                ldsm4(ah[mt][0], ah[mt][1], ah[mt][2], ah[mt][3], a_h + ar + kofA);
                ldsm4(al[mt][0], al[mt][1], al[mt][2], al[mt][3], a_l + ar + kofA);
            }
#pragma unroll
            for (int np = 0; np < 4; np++) {
                u32 br = (u32)((wn * 64 + np * 16 + bn_lane) * RSB);
                u32 h0, h1, h2, h3, l0, l1, l2, l3;
                ldsm4(h0, h1, h2, h3, b_h + br + kofB);
                ldsm4(l0, l1, l2, l3, b_l + br + kofB);
#pragma unroll
                for (int mt = 0; mt < 2; mt++) {
                    mma16816(acc[mt][np * 2],     ah[mt], h0, h1);
                    mma16816(acc[mt][np * 2 + 1], ah[mt], h2, h3);
                    mma16816(acc[mt][np * 2],     ah[mt], l0, l1);
                    mma16816(acc[mt][np * 2 + 1], ah[mt], l2, l3);
                    mma16816(acc[mt][np * 2],     al[mt], h0, h1);
                    mma16816(acc[mt][np * 2 + 1], al[mt], h2, h3);
                }
            }
        }

        __syncthreads();
        if (c + NSTG < NCHUNK) {
            cp_chunk(stg, Ah, Al, Bh, Bl, t, (c + NSTG) * 32);
            asm volatile("cp.async.commit_group;" ::: "memory");
        }
    }

    const int gid = lane >> 2, tig = lane & 3;
#pragma unroll
    for (int mt = 0; mt < 2; mt++) {
#pragma unroll
        for (int nt = 0; nt < 8; nt++) {
            int r = m0 + wm * 32 + mt * 16 + gid;
            int cc = n0 + wn * 64 + nt * 8 + tig * 2;
            if (MODE == 0) {
                *(float2*)(Cf + (size_t)r * DMODEL + cc) =
                    make_float2(acc[mt][nt][0], acc[mt][nt][1]);
                *(float2*)(Cf + (size_t)(r + 8) * DMODEL + cc) =
                    make_float2(acc[mt][nt][2], acc[mt][nt][3]);
            } else {
                hilo_store(Ch, Cl, (size_t)r * DMODEL + cc,
                           acc[mt][nt][0], acc[mt][nt][1]);
                hilo_store(Ch, Cl, (size_t)(r + 8) * DMODEL + cc,
                           acc[mt][nt][2], acc[mt][nt][3]);
            }
        }
    }
}

__global__ __launch_bounds__(256, 1)
void gemm_qkv_mma() {
    int bx = blockIdx.x;              // 24 = 3 matrices x 8 column tiles
    int sel = bx >> 3, bn = bx & 7;
    __nv_bfloat16* Ch = (sel == 0) ? g_Qh : (sel == 1) ? g_Kh : g_Vh;
    __nv_bfloat16* Cl = (sel == 0) ? g_Ql : (sel == 1) ? g_Kl : g_Vl;
    gemm_mma_body<1>(g_Xhi, g_Xlo, g_Wth[sel], g_Wtl[sel],
                     nullptr, Ch, Cl, blockIdx.y, bn);
}

__global__ __launch_bounds__(256, 1)
void gemm_o_mma(float* __restrict__ Cout) {
    gemm_mma_body<0>(g_Chi, g_Clo, g_Wth[3], g_Wtl[3],
                     Cout, nullptr, nullptr, blockIdx.y, blockIdx.x);
}

// ---------------- MMA flash attention -------------------------------------
// smem: 2 stages x {Kh, Kl, Vh, Vl}[128 rows][72 bf16 = 144B] + bias strip
#define ARS       144
#define AK_KH     0
#define AK_KL     18432
#define AK_VH     36864
#define AK_VL     55296
#define ASTG      73728
#define STRIP_OFF (2 * ASTG)             // 147456
#define ATTN_SMEM (2 * ASTG + 2048)      // 149504

__device__ __forceinline__ void attn_cp_tile(u32 stg, int rowbase, int hcol, int t) {
#pragma unroll
    for (int u = 0; u < 4; u++) {
        int c = t + u * 256; int row = c >> 3, seg = c & 7;
        size_t src = (size_t)(rowbase + row) * DMODEL + hcol + seg * 8;
        u32 d = stg + row * ARS + seg * 16;
        cp16(d + AK_KH, g_Kh + src);
        cp16(d + AK_KL, g_Kl + src);
        cp16(d + AK_VH, g_Vh + src);
        cp16(d + AK_VL, g_Vl + src);
    }
}

__global__ __launch_bounds__(256, 1)
void attn_mma_kernel() {
    extern __shared__ char sm[];
    const u32 sb = smem_u32(sm);
    const int t = threadIdx.x, w = t >> 5, lane = t & 31;
    const int q0 = blockIdx.x * 128;
    const int bh = blockIdx.y;
    const int b = bh >> 4, h = bh & 15;
    const int row0 = b * SEQ;
    const int hcol = h * DK;

    const int gid = lane >> 2, tig = lane & 3;
    const int r15 = lane & 15, kh = lane >> 4;
    const int bn_lane = ((lane >> 4) << 3) + (lane & 7);
    const int bkh = (lane >> 3) & 1;
    const int vrow_l = (((lane >> 3) & 1) << 3) + (lane & 7);
    const int vcol_l = (lane >> 4) << 4;

    // ---- stage Q into stage0's K slots, extract A-fragments ----
#pragma unroll
    for (int u = 0; u < 4; u++) {
        int c = t + u * 256; int row = c >> 3, seg = c & 7;
        size_t src = (size_t)(row0 + q0 + row) * DMODEL + hcol + seg * 8;
        cp16(sb + AK_KH + row * ARS + seg * 16, g_Qh + src);
        cp16(sb + AK_KL + row * ARS + seg * 16, g_Ql + src);
    }
    asm volatile("cp.async.commit_group;" ::: "memory");
    asm volatile("cp.async.wait_group 0;" ::: "memory");
    __syncthreads();

    u32 qah[4][4], qal[4][4];
#pragma unroll
    for (int ks = 0; ks < 4; ks++) {
        u32 ar = (u32)((w * 16 + r15) * ARS + (ks * 16 + kh * 8) * 2);
        ldsm4(qah[ks][0], qah[ks][1], qah[ks][2], qah[ks][3], sb + AK_KH + ar);
        ldsm4(qal[ks][0], qal[ks][1], qal[ks][2], qal[ks][3], sb + AK_KL + ar);
    }
    __syncthreads();

    attn_cp_tile(sb,        row0,       hcol, t);
    asm volatile("cp.async.commit_group;" ::: "memory");
    attn_cp_tile(sb + ASTG, row0 + 128, hcol, t);
    asm volatile("cp.async.commit_group;" ::: "memory");

    float s[16][4], o[8][4];
    float m0 = -1e30f, m1 = -1e30f, l0 = 0.f, l1 = 0.f;
#pragma unroll
    for (int i = 0; i < 8; i++) { o[i][0] = o[i][1] = o[i][2] = o[i][3] = 0.f; }

    const int ii0 = w * 16 + gid;

#pragma unroll 1
    for (int kt = 0; kt < 16; kt++) {
        if (kt < 14) asm volatile("cp.async.wait_group 1;" ::: "memory");
        else         asm volatile("cp.async.wait_group 0;" ::: "memory");
        __syncthreads();

        // bias strip (float2-duplicated for aligned LDS.64)
        {
            int rel = kt * 128 - q0 + t - 127 + 2047;
            int r2 = rel + 1;
            if (rel > 4095) rel = 4095;
            if (r2  > 4095) r2  = 4095;
            float b0v = g_biasTab[h * 4096 + rel];
            float b1v = g_biasTab[h * 4096 + r2];
            *(float2*)(sm + STRIP_OFF + t * 8) = make_float2(b0v, b1v);
        }

        const u32 stg = sb + (kt & 1) * ASTG;
#pragma unroll
        for (int nt = 0; nt < 16; nt++) { s[nt][0] = s[nt][1] = s[nt][2] = s[nt][3] = 0.f; }

        // S = Q @ K^T (3-pass)
#pragma unroll
        for (int ks = 0; ks < 4; ks++) {
#pragma unroll
            for (int np = 0; np < 8; np++) {
                u32 br = (u32)((np * 16 + bn_lane) * ARS + (ks * 16 + bkh * 8) * 2);
                u32 h0, h1, h2, h3, e0, e1, e2, e3;
                ldsm4(h0, h1, h2, h3, stg + AK_KH + br);
                ldsm4(e0, e1, e2, e3, stg + AK_KL + br);
                mma16816(s[2 * np],     qah[ks], h0, h1);
                mma16816(s[2 * np + 1], qah[ks], h2, h3);
                mma16816(s[2 * np],     qah[ks], e0, e1);
                mma16816(s[2 * np + 1], qah[ks], e2, e3);
                mma16816(s[2 * np],     qal[ks], h0, h1);
                mma16816(s[2 * np + 1], qal[ks], h2, h3);
            }
        }
        __syncthreads();   // strip visible to all lanes

        // bias + online softmax (rows gid / gid+8 live in 4-lane groups)
        float rm0 = -1e30f, rm1 = -1e30f;
#pragma unroll
        for (int nt = 0; nt < 16; nt++) {
            int d0 = nt * 8 + tig * 2 - ii0 + 127;
            float2 bA = *(float2*)(sm + STRIP_OFF + d0 * 8);
            float2 bB = *(float2*)(sm + STRIP_OFF + (d0 - 8) * 8);
            s[nt][0] += bA.x; s[nt][1] += bA.y;
            s[nt][2] += bB.x; s[nt][3] += bB.y;
            rm0 = fmaxf(rm0, fmaxf(s[nt][0], s[nt][1]));
            rm1 = fmaxf(rm1, fmaxf(s[nt][2], s[nt][3]));
        }
        rm0 = fmaxf(rm0, __shfl_xor_sync(0xffffffffu, rm0, 1));
        rm0 = fmaxf(rm0, __shfl_xor_sync(0xffffffffu, rm0, 2));
        rm1 = fmaxf(rm1, __shfl_xor_sync(0xffffffffu, rm1, 1));
        rm1 = fmaxf(rm1, __shfl_xor_sync(0xffffffffu, rm1, 2));
        float mn0 = fmaxf(m0, rm0), mn1 = fmaxf(m1, rm1);
        float fr0 = __expf(m0 - mn0), fr1 = __expf(m1 - mn1);
        m0 = mn0; m1 = mn1;
        float sum0 = 0.f, sum1 = 0.f;
#pragma unroll
        for (int nt = 0; nt < 16; nt++) {
            s[nt][0] = __expf(s[nt][0] - mn0);
            s[nt][1] = __expf(s[nt][1] - mn0);
            s[nt][2] = __expf(s[nt][2] - mn1);
            s[nt][3] = __expf(s[nt][3] - mn1);
            sum0 += s[nt][0] + s[nt][1];
            sum1 += s[nt][2] + s[nt][3];
        }
        sum0 += __shfl_xor_sync(0xffffffffu, sum0, 1);
        sum0 += __shfl_xor_sync(0xffffffffu, sum0, 2);
        sum1 += __shfl_xor_sync(0xffffffffu, sum1, 1);
        sum1 += __shfl_xor_sync(0xffffffffu, sum1, 2);
        l0 = l0 * fr0 + sum0;
        l1 = l1 * fr1 + sum1;
#pragma unroll
        for (int nt = 0; nt < 8; nt++) {
            o[nt][0] *= fr0; o[nt][1] *= fr0; o[nt][2] *= fr1; o[nt][3] *= fr1;
        }

        // O += P @ V  (P passes in registers; 3-pass)
#pragma unroll
        for (int ks2 = 0; ks2 < 8; ks2++) {
            u32 ph[4], pl[4];
            ph[0] = pk2(s[2 * ks2][0],     s[2 * ks2][1]);
            ph[1] = pk2(s[2 * ks2][2],     s[2 * ks2][3]);
            ph[2] = pk2(s[2 * ks2 + 1][0], s[2 * ks2 + 1][1]);
            ph[3] = pk2(s[2 * ks2 + 1][2], s[2 * ks2 + 1][3]);
#pragma unroll
            for (int q = 0; q < 4; q++) {
                const float* sp = &s[2 * ks2 + (q >> 1)][(q & 1) * 2];
                float f0 = __uint_as_float(ph[q] << 16);
                float f1 = __uint_as_float(ph[q] & 0xffff0000u);
                pl[q] = pk2(sp[0] - f0, sp[1] - f1);
            }
#pragma unroll
            for (int np2 = 0; np2 < 4; np2++) {
                u32 va = stg + (u32)((ks2 * 16 + vrow_l) * ARS + np2 * 32 + vcol_l);
                u32 h0, h1, h2, h3, e0, e1, e2, e3;
                ldsm4t(h0, h1, h2, h3, va + AK_VH);
                ldsm4t(e0, e1, e2, e3, va + AK_VL);
                mma16816(o[2 * np2],     ph, h0, h1);
                mma16816(o[2 * np2 + 1], ph, h2, h3);
                mma16816(o[2 * np2],     pl, h0, h1);
                mma16816(o[2 * np2 + 1], pl, h2, h3);
                mma16816(o[2 * np2],     ph, e0, e1);
                mma16816(o[2 * np2 + 1], ph, e2, e3);
            }
        }
        __syncthreads();   // stage fully consumed
        if (kt + 2 < 16) {
            attn_cp_tile(sb + (kt & 1) * ASTG, row0 + (kt + 2) * 128, hcol, t);
            asm volatile("cp.async.commit_group;" ::: "memory");
        }
    }

    // epilogue: normalize, write ctx as bf16 hi/lo
    float inv0 = 1.0f / l0, inv1 = 1.0f / l1;
    int r0 = row0 + q0 + w * 16 + gid;
#pragma unroll
    for (int nt = 0; nt < 8; nt++) {
        int cc = hcol + nt * 8 + tig * 2;
        hilo_store(g_Chi, g_Clo, (size_t)r0 * DMODEL + cc,
                   o[nt][0] * inv0, o[nt][1] * inv0);
        hilo_store(g_Chi, g_Clo, (size_t)(r0 + 8) * DMODEL + cc,
                   o[nt][2] * inv1, o[nt][3] * inv1);
    }
}

// ---------------- launch ----------------
extern "C" void kernel_launch(void* const* d_in, const int* in_sizes, int n_in,
                              void* d_out, int out_size) {
    const float* X   = (const float*)d_in[0];
    const float* Wq  = (const float*)d_in[1];
    const float* Wk  = (const float*)d_in[2];
    const float* Wv  = (const float*)d_in[3];
    const float* Wo  = (const float*)d_in[4];
    const float* rbi = (const float*)d_in[5];
    float* out = (float*)d_out;

    cudaFuncSetAttribute(gemm_qkv_mma, cudaFuncAttributeMaxDynamicSharedMemorySize,
                         GEMM_SMEM);
    cudaFuncSetAttribute(gemm_o_mma, cudaFuncAttributeMaxDynamicSharedMemorySize,
                         GEMM_SMEM);
    cudaFuncSetAttribute(attn_mma_kernel, cudaFuncAttributeMaxDynamicSharedMemorySize,
                         ATTN_SMEM);

    bias_table_kernel<<<(HEADS * 4095 + 255) / 256, 256>>>(rbi);
    wconv_kernel<<<dim3(32, 32, 4), dim3(32, 8)>>>(Wq, Wk, Wv, Wo);
    xsplit_kernel<<<MROWS * DMODEL / 1024, 256>>>(X);

    gemm_qkv_mma<<<dim3(24, MROWS / 128), 256, GEMM_SMEM>>>();

    attn_mma_kernel<<<dim3(SEQ / 128, BATCH * HEADS), 256, ATTN_SMEM>>>();

    gemm_o_mma<<<dim3(DMODEL / 128, MROWS / 128), 256, GEMM_SMEM>>>(out);
}

// round 16
// speedup vs baseline: 3.1719x; 1.0803x over previous
#include <cuda_runtime.h>
#include <cuda_bf16.h>
#include <math.h>

#define BATCH   2
#define SEQ     2048
#define DMODEL  1024
#define HEADS   16
#define DK      64
#define MROWS   (BATCH * SEQ)      // 4096

typedef unsigned long long ull;
typedef unsigned int u32;

// ---------------- warp-MMA helpers (baseline PTX, works on compute_103) ----
__device__ __forceinline__ u32 smem_u32(const void* p) {
    u32 a;
    asm("{ .reg .u64 t; cvta.to.shared.u64 t, %1; cvt.u32.u64 %0, t; }"
        : "=r"(a) : "l"(p));
    return a;
}
__device__ __forceinline__ void ldsm4(u32& r0, u32& r1, u32& r2, u32& r3, u32 addr) {
    asm volatile("ldmatrix.sync.aligned.m8n8.x4.shared.b16 {%0,%1,%2,%3}, [%4];"
                 : "=r"(r0), "=r"(r1), "=r"(r2), "=r"(r3) : "r"(addr));
}
__device__ __forceinline__ void ldsm4t(u32& r0, u32& r1, u32& r2, u32& r3, u32 addr) {
    asm volatile("ldmatrix.sync.aligned.m8n8.x4.trans.shared.b16 {%0,%1,%2,%3}, [%4];"
                 : "=r"(r0), "=r"(r1), "=r"(r2), "=r"(r3) : "r"(addr));
}
__device__ __forceinline__ void mma16816(float* c, const u32* a, u32 b0, u32 b1) {
    asm volatile("mma.sync.aligned.m16n8k16.row.col.f32.bf16.bf16.f32 "
                 "{%0,%1,%2,%3}, {%4,%5,%6,%7}, {%8,%9}, {%0,%1,%2,%3};"
                 : "+f"(c[0]), "+f"(c[1]), "+f"(c[2]), "+f"(c[3])
                 : "r"(a[0]), "r"(a[1]), "r"(a[2]), "r"(a[3]), "r"(b0), "r"(b1));
}
__device__ __forceinline__ void cp16(u32 dst, const void* src) {
    asm volatile("cp.async.cg.shared.global [%0], [%1], 16;"
                 :: "r"(dst), "l"(__cvta_generic_to_global(src)));
}
// pack two f32 -> bf16x2 (lo half = first arg)
__device__ __forceinline__ u32 pk2(float lo, float hi) {
    u32 d; asm("cvt.rn.bf16x2.f32 %0, %1, %2;" : "=r"(d) : "f"(hi), "f"(lo));
    return d;
}
__device__ __forceinline__ void hilo_store(__nv_bfloat16* Ch, __nv_bfloat16* Cl,
                                           size_t off, float v0, float v1) {
    u32 hi = pk2(v0, v1);
    float f0 = __uint_as_float(hi << 16);
    float f1 = __uint_as_float(hi & 0xffff0000u);
    u32 lo = pk2(v0 - f0, v1 - f1);
    *(u32*)(Ch + off) = hi;
    *(u32*)(Cl + off) = lo;
}

// ---------------- scratch (device globals: allocation-free) ----------------
__device__ float g_biasTab[HEADS * 4096];                 // [h][rp + 2047]
__device__ __nv_bfloat16 g_Xhi[MROWS * DMODEL];
__device__ __nv_bfloat16 g_Xlo[MROWS * DMODEL];
__device__ __nv_bfloat16 g_Qh[MROWS * DMODEL];
__device__ __nv_bfloat16 g_Ql[MROWS * DMODEL];
__device__ __nv_bfloat16 g_Kh[MROWS * DMODEL];
__device__ __nv_bfloat16 g_Kl[MROWS * DMODEL];
__device__ __nv_bfloat16 g_Vh[MROWS * DMODEL];
__device__ __nv_bfloat16 g_Vl[MROWS * DMODEL];
__device__ __nv_bfloat16 g_Chi[MROWS * DMODEL];           // ctx hi/lo
__device__ __nv_bfloat16 g_Clo[MROWS * DMODEL];
__device__ __nv_bfloat16 g_Wth[4][DMODEL * DMODEL];       // W^T hi, [n][k]
__device__ __nv_bfloat16 g_Wtl[4][DMODEL * DMODEL];       // W^T lo, [n][k]

// ---------------- T5 relative-position bias table ----------------
__global__ void bias_table_kernel(const float* __restrict__ rel_bias) {
    int idx = blockIdx.x * blockDim.x + threadIdx.x;
    if (idx >= HEADS * 4095) return;
    int h  = idx / 4095;
    int i  = idx % 4095;
    int rp = i - 2047;
    int rb  = (rp > 0) ? 16 : 0;
    int rpa = rp < 0 ? -rp : rp;
    int bkt;
    if (rpa < 8) {
        bkt = rpa;
    } else {
        float t = logf((float)rpa * 0.125f);
        t = t / 2.7725887222397812f;
        t = t * 8.0f;
        bkt = 8 + (int)t;
        if (bkt > 15) bkt = 15;
    }
    g_biasTab[h * 4096 + i] = rel_bias[(rb + bkt) * HEADS + h];
}

// ---------------- weight transpose + bf16 hi/lo split prepass ----------------
__global__ void wconv_kernel(const float* __restrict__ Wq, const float* __restrict__ Wk,
                             const float* __restrict__ Wv, const float* __restrict__ Wo) {
    __shared__ float tile[32][33];
    int z = blockIdx.z;
    const float* W = (z == 0) ? Wq : (z == 1) ? Wk : (z == 2) ? Wv : Wo;
    __nv_bfloat16* Oh = g_Wth[z];
    __nv_bfloat16* Ol = g_Wtl[z];
    int x0 = blockIdx.x * 32, y0 = blockIdx.y * 32;
    int tx = threadIdx.x, ty = threadIdx.y;
#pragma unroll
    for (int i = 0; i < 4; i++)
        tile[ty + i * 8][tx] = W[(size_t)(y0 + ty + i * 8) * DMODEL + x0 + tx];
    __syncthreads();
#pragma unroll
    for (int i = 0; i < 4; i++) {
        float v = tile[tx][ty + i * 8];
        int n = x0 + ty + i * 8, k = y0 + tx;
        __nv_bfloat16 h = __float2bfloat16(v);
        float lo = v - __bfloat162float(h);
        Oh[(size_t)n * DMODEL + k] = h;
        Ol[(size_t)n * DMODEL + k] = __float2bfloat16(lo);
    }
}

// ---------------- X hi/lo split prepass ----------------
__global__ void xsplit_kernel(const float* __restrict__ X) {
    int i = (blockIdx.x * 256 + threadIdx.x) * 4;
    float4 v = *(const float4*)(X + i);
    __nv_bfloat162 h0 = __floats2bfloat162_rn(v.x, v.y);
    __nv_bfloat162 h1 = __floats2bfloat162_rn(v.z, v.w);
    float2 f0 = __bfloat1622float2(h0);
    float2 f1 = __bfloat1622float2(h1);
    __nv_bfloat162 l0 = __floats2bfloat162_rn(v.x - f0.x, v.y - f0.y);
    __nv_bfloat162 l1 = __floats2bfloat162_rn(v.z - f1.x, v.w - f1.y);
    *(__nv_bfloat162*)(g_Xhi + i)     = h0;
    *(__nv_bfloat162*)(g_Xhi + i + 2) = h1;
    *(__nv_bfloat162*)(g_Xlo + i)     = l0;
    *(__nv_bfloat162*)(g_Xlo + i + 2) = l1;
}

// ---------------- MMA GEMM: CTA 128x256, warp 64x64 (3-pass bf16) ---------
#define RSB     80
#define A_SZ    (128 * RSB)              // 10240
#define B_SZ    (256 * RSB)              // 20480
#define OFF_AH  0
#define OFF_AL  A_SZ
#define OFF_BH  (2 * A_SZ)
#define OFF_BL  (2 * A_SZ + B_SZ)
#define STG_SZ  (2 * A_SZ + 2 * B_SZ)    // 61440
#define NSTG    3
#define GEMM_SMEM (NSTG * STG_SZ)        // 184320
#define NCHUNK  (DMODEL / 32)            // 32

__device__ __forceinline__ void cp_chunk(
    u32 stg,
    const __nv_bfloat16* __restrict__ Ah, const __nv_bfloat16* __restrict__ Al,
    const __nv_bfloat16* __restrict__ Bh, const __nv_bfloat16* __restrict__ Bl,
    int t, int k0)
{
    // A: 128 rows x 64B, hi+lo
#pragma unroll
    for (int u = 0; u < 2; u++) {
        const int id = t + u * 256;              // 0..511
        const int row = id >> 2, seg = id & 3;
        const size_t src = (size_t)row * DMODEL + k0 + seg * 8;
        const u32 d = stg + row * RSB + seg * 16;
        cp16(d + OFF_AH, Ah + src);
        cp16(d + OFF_AL, Al + src);
    }
    // B: 256 rows x 64B, hi+lo
#pragma unroll
    for (int u = 0; u < 4; u++) {
        const int id = t + u * 256;              // 0..1023
        const int row = id >> 2, seg = id & 3;
        const size_t src = (size_t)row * DMODEL + k0 + seg * 8;
        const u32 d = stg + row * RSB + seg * 16;
        cp16(d + OFF_BH, Bh + src);
        cp16(d + OFF_BL, Bl + src);
    }
}

// MODE 0: f32 output to Cf.  MODE 1: bf16 hi/lo output to Ch/Cl.
template<int MODE>
__device__ __forceinline__ void gemm_mma_body(
    const __nv_bfloat16* __restrict__ Ah_g, const __nv_bfloat16* __restrict__ Al_g,
    const __nv_bfloat16* __restrict__ Bh_g, const __nv_bfloat16* __restrict__ Bl_g,
    float* __restrict__ Cf, __nv_bfloat16* __restrict__ Ch,
    __nv_bfloat16* __restrict__ Cl, int bm, int bn)
{
    extern __shared__ char sm[];
    const u32 sb = smem_u32(sm);
    const int t = threadIdx.x, wid = t >> 5, lane = t & 31;
    const int wm = wid & 1, wn = wid >> 1;        // 2x4 warp grid, 64x64 tiles
    const int m0 = bm * 128, n0 = bn * 256;

    const __nv_bfloat16* Ah = Ah_g + (size_t)m0 * DMODEL;
    const __nv_bfloat16* Al = Al_g + (size_t)m0 * DMODEL;
    const __nv_bfloat16* Bh = Bh_g + (size_t)n0 * DMODEL;
    const __nv_bfloat16* Bl = Bl_g + (size_t)n0 * DMODEL;

    float acc[4][8][4];
#pragma unroll
    for (int i = 0; i < 4; i++)
#pragma unroll
        for (int j = 0; j < 8; j++)
#pragma unroll
            for (int q = 0; q < 4; q++) acc[i][j][q] = 0.f;

    const int r15 = lane & 15, kh = lane >> 4;
    const int bn_lane = ((lane >> 4) << 3) + (lane & 7);
    const int bkh = (lane >> 3) & 1;

    cp_chunk(sb,              Ah, Al, Bh, Bl, t, 0);
    asm volatile("cp.async.commit_group;" ::: "memory");
    cp_chunk(sb + STG_SZ,     Ah, Al, Bh, Bl, t, 32);
    asm volatile("cp.async.commit_group;" ::: "memory");
    cp_chunk(sb + 2 * STG_SZ, Ah, Al, Bh, Bl, t, 64);
    asm volatile("cp.async.commit_group;" ::: "memory");

#pragma unroll 1
    for (int c = 0; c < NCHUNK; c++) {
        if (c < NCHUNK - 2)      asm volatile("cp.async.wait_group 2;" ::: "memory");
        else if (c == NCHUNK - 2) asm volatile("cp.async.wait_group 1;" ::: "memory");
        else                      asm volatile("cp.async.wait_group 0;" ::: "memory");
        __syncthreads();

        const u32 stg = sb + (c % NSTG) * STG_SZ;
        const u32 a_h = stg + OFF_AH, a_l = stg + OFF_AL;
        const u32 b_h = stg + OFF_BH, b_l = stg + OFF_BL;

#pragma unroll
        for (int ks = 0; ks < 2; ks++) {
            const u32 kofA = (u32)((ks * 16 + kh * 8) * 2);
            const u32 kofB = (u32)((ks * 16 + bkh * 8) * 2);
            u32 ah[4][4], al[4][4];
#pragma unroll
            for (int mt = 0; mt < 4; mt++) {
                u32 ar = (u32)((wm * 64 + mt * 16 + r15) * RSB);
                ldsm4(ah[mt][0], ah[mt][1], ah[mt][2], ah[mt][3], a_h + ar + kofA);
                ldsm4(al[mt][0], al[mt][1], al[mt][2], al[mt][3], a_l + ar + kofA);
            }
#pragma unroll
            for (int np = 0; np < 4; np++) {
                u32 br = (u32)((wn * 64 + np * 16 + bn_lane) * RSB);
                u32 h0, h1, h2, h3, l0, l1, l2, l3;
                ldsm4(h0, h1, h2, h3, b_h + br + kofB);
                ldsm4(l0, l1, l2, l3, b_l + br + kofB);
#pragma unroll
                for (int mt = 0; mt < 4; mt++) {
                    mma16816(acc[mt][np * 2],     ah[mt], h0, h1);
                    mma16816(acc[mt][np * 2 + 1], ah[mt], h2, h3);
                    mma16816(acc[mt][np * 2],     ah[mt], l0, l1);
                    mma16816(acc[mt][np * 2 + 1], ah[mt], l2, l3);
                    mma16816(acc[mt][np * 2],     al[mt], h0, h1);
                    mma16816(acc[mt][np * 2 + 1], al[mt], h2, h3);
                }
            }
        }

        __syncthreads();
        if (c + NSTG < NCHUNK) {
            cp_chunk(stg, Ah, Al, Bh, Bl, t, (c + NSTG) * 32);
            asm volatile("cp.async.commit_group;" ::: "memory");
        }
    }

    const int gid = lane >> 2, tig = lane & 3;
#pragma unroll
    for (int mt = 0; mt < 4; mt++) {
#pragma unroll
        for (int nt = 0; nt < 8; nt++) {
            int r = m0 + wm * 64 + mt * 16 + gid;
            int cc = n0 + wn * 64 + nt * 8 + tig * 2;
            if (MODE == 0) {
                *(float2*)(Cf + (size_t)r * DMODEL + cc) =
                    make_float2(acc[mt][nt][0], acc[mt][nt][1]);
                *(float2*)(Cf + (size_t)(r + 8) * DMODEL + cc) =
                    make_float2(acc[mt][nt][2], acc[mt][nt][3]);
            } else {
                hilo_store(Ch, Cl, (size_t)r * DMODEL + cc,
                           acc[mt][nt][0], acc[mt][nt][1]);
                hilo_store(Ch, Cl, (size_t)(r + 8) * DMODEL + cc,
                           acc[mt][nt][2], acc[mt][nt][3]);
            }
        }
    }
}

__global__ __launch_bounds__(256, 1)
void gemm_qkv_mma() {
    int bx = blockIdx.x;              // 12 = 3 matrices x 4 column tiles
    int sel = bx >> 2, bn = bx & 3;
    __nv_bfloat16* Ch = (sel == 0) ? g_Qh : (sel == 1) ? g_Kh : g_Vh;
    __nv_bfloat16* Cl = (sel == 0) ? g_Ql : (sel == 1) ? g_Kl : g_Vl;
    gemm_mma_body<1>(g_Xhi, g_Xlo, g_Wth[sel], g_Wtl[sel],
                     nullptr, Ch, Cl, blockIdx.y, bn);
}

__global__ __launch_bounds__(256, 1)
void gemm_o_mma(float* __restrict__ Cout) {
    gemm_mma_body<0>(g_Chi, g_Clo, g_Wth[3], g_Wtl[3],
                     Cout, nullptr, nullptr, blockIdx.y, blockIdx.x);
}

// ---------------- MMA flash attention -------------------------------------
// smem: 2 stages x {Kh, Kl, Vh, Vl}[128 rows][72 bf16 = 144B] + bias strip
#define ARS       144
#define AK_KH     0
#define AK_KL     18432
#define AK_VH     36864
#define AK_VL     55296
#define ASTG      73728
#define STRIP_OFF (2 * ASTG)             // 147456
#define ATTN_SMEM (2 * ASTG + 2048)      // 149504

__device__ __forceinline__ void attn_cp_tile(u32 stg, int rowbase, int hcol, int t) {
#pragma unroll
    for (int u = 0; u < 4; u++) {
        int c = t + u * 256; int row = c >> 3, seg = c & 7;
        size_t src = (size_t)(rowbase + row) * DMODEL + hcol + seg * 8;
        u32 d = stg + row * ARS + seg * 16;
        cp16(d + AK_KH, g_Kh + src);
        cp16(d + AK_KL, g_Kl + src);
        cp16(d + AK_VH, g_Vh + src);
        cp16(d + AK_VL, g_Vl + src);
    }
}

__global__ __launch_bounds__(256, 1)
void attn_mma_kernel() {
    extern __shared__ char sm[];
    const u32 sb = smem_u32(sm);
    const int t = threadIdx.x, w = t >> 5, lane = t & 31;
    const int q0 = blockIdx.x * 128;
    const int bh = blockIdx.y;
    const int b = bh >> 4, h = bh & 15;
    const int row0 = b * SEQ;
    const int hcol = h * DK;

    const int gid = lane >> 2, tig = lane & 3;
    const int r15 = lane & 15, kh = lane >> 4;
    const int bn_lane = ((lane >> 4) << 3) + (lane & 7);
    const int bkh = (lane >> 3) & 1;
    const int vrow_l = (((lane >> 3) & 1) << 3) + (lane & 7);
    const int vcol_l = (lane >> 4) << 4;

    // ---- stage Q into stage0's K slots, extract A-fragments ----
#pragma unroll
    for (int u = 0; u < 4; u++) {
        int c = t + u * 256; int row = c >> 3, seg = c & 7;
        size_t src = (size_t)(row0 + q0 + row) * DMODEL + hcol + seg * 8;
        cp16(sb + AK_KH + row * ARS + seg * 16, g_Qh + src);
        cp16(sb + AK_KL + row * ARS + seg * 16, g_Ql + src);
    }
    asm volatile("cp.async.commit_group;" ::: "memory");
    asm volatile("cp.async.wait_group 0;" ::: "memory");
    __syncthreads();

    u32 qah[4][4], qal[4][4];
#pragma unroll
    for (int ks = 0; ks < 4; ks++) {
        u32 ar = (u32)((w * 16 + r15) * ARS + (ks * 16 + kh * 8) * 2);
        ldsm4(qah[ks][0], qah[ks][1], qah[ks][2], qah[ks][3], sb + AK_KH + ar);
        ldsm4(qal[ks][0], qal[ks][1], qal[ks][2], qal[ks][3], sb + AK_KL + ar);
    }
    __syncthreads();

    attn_cp_tile(sb,        row0,       hcol, t);
    asm volatile("cp.async.commit_group;" ::: "memory");
    attn_cp_tile(sb + ASTG, row0 + 128, hcol, t);
    asm volatile("cp.async.commit_group;" ::: "memory");

    float s[16][4], o[8][4];
    float m0 = -1e30f, m1 = -1e30f, l0 = 0.f, l1 = 0.f;
#pragma unroll
    for (int i = 0; i < 8; i++) { o[i][0] = o[i][1] = o[i][2] = o[i][3] = 0.f; }

    const int ii0 = w * 16 + gid;

#pragma unroll 1
    for (int kt = 0; kt < 16; kt++) {
        if (kt < 14) asm volatile("cp.async.wait_group 1;" ::: "memory");
        else         asm volatile("cp.async.wait_group 0;" ::: "memory");
        __syncthreads();

        // bias strip (float2-duplicated for aligned LDS.64)
        {
            int rel = kt * 128 - q0 + t - 127 + 2047;
            int r2 = rel + 1;
            if (rel > 4095) rel = 4095;
            if (r2  > 4095) r2  = 4095;
            float b0v = g_biasTab[h * 4096 + rel];
            float b1v = g_biasTab[h * 4096 + r2];
            *(float2*)(sm + STRIP_OFF + t * 8) = make_float2(b0v, b1v);
        }

        const u32 stg = sb + (kt & 1) * ASTG;
#pragma unroll
        for (int nt = 0; nt < 16; nt++) { s[nt][0] = s[nt][1] = s[nt][2] = s[nt][3] = 0.f; }

        // S = Q @ K^T (3-pass)
#pragma unroll
        for (int ks = 0; ks < 4; ks++) {
#pragma unroll
            for (int np = 0; np < 8; np++) {
                u32 br = (u32)((np * 16 + bn_lane) * ARS + (ks * 16 + bkh * 8) * 2);
                u32 h0, h1, h2, h3, e0, e1, e2, e3;
                ldsm4(h0, h1, h2, h3, stg + AK_KH + br);
                ldsm4(e0, e1, e2, e3, stg + AK_KL + br);
                mma16816(s[2 * np],     qah[ks], h0, h1);
                mma16816(s[2 * np + 1], qah[ks], h2, h3);
                mma16816(s[2 * np],     qah[ks], e0, e1);
                mma16816(s[2 * np + 1], qah[ks], e2, e3);
                mma16816(s[2 * np],     qal[ks], h0, h1);
                mma16816(s[2 * np + 1], qal[ks], h2, h3);
            }
        }
        __syncthreads();   // strip visible to all lanes

        // bias + online softmax (rows gid / gid+8 live in 4-lane groups)
        float rm0 = -1e30f, rm1 = -1e30f;
#pragma unroll
        for (int nt = 0; nt < 16; nt++) {
            int d0 = nt * 8 + tig * 2 - ii0 + 127;
            float2 bA = *(float2*)(sm + STRIP_OFF + d0 * 8);
            float2 bB = *(float2*)(sm + STRIP_OFF + (d0 - 8) * 8);
            s[nt][0] += bA.x; s[nt][1] += bA.y;
            s[nt][2] += bB.x; s[nt][3] += bB.y;
            rm0 = fmaxf(rm0, fmaxf(s[nt][0], s[nt][1]));
            rm1 = fmaxf(rm1, fmaxf(s[nt][2], s[nt][3]));
        }
        rm0 = fmaxf(rm0, __shfl_xor_sync(0xffffffffu, rm0, 1));
        rm0 = fmaxf(rm0, __shfl_xor_sync(0xffffffffu, rm0, 2));
        rm1 = fmaxf(rm1, __shfl_xor_sync(0xffffffffu, rm1, 1));
        rm1 = fmaxf(rm1, __shfl_xor_sync(0xffffffffu, rm1, 2));
        float mn0 = fmaxf(m0, rm0), mn1 = fmaxf(m1, rm1);
        float fr0 = __expf(m0 - mn0), fr1 = __expf(m1 - mn1);
        m0 = mn0; m1 = mn1;
        float sum0 = 0.f, sum1 = 0.f;
#pragma unroll
        for (int nt = 0; nt < 16; nt++) {
            s[nt][0] = __expf(s[nt][0] - mn0);
            s[nt][1] = __expf(s[nt][1] - mn0);
            s[nt][2] = __expf(s[nt][2] - mn1);
            s[nt][3] = __expf(s[nt][3] - mn1);
            sum0 += s[nt][0] + s[nt][1];
            sum1 += s[nt][2] + s[nt][3];
        }
        sum0 += __shfl_xor_sync(0xffffffffu, sum0, 1);
        sum0 += __shfl_xor_sync(0xffffffffu, sum0, 2);
        sum1 += __shfl_xor_sync(0xffffffffu, sum1, 1);
        sum1 += __shfl_xor_sync(0xffffffffu, sum1, 2);
        l0 = l0 * fr0 + sum0;
        l1 = l1 * fr1 + sum1;
#pragma unroll
        for (int nt = 0; nt < 8; nt++) {
            o[nt][0] *= fr0; o[nt][1] *= fr0; o[nt][2] *= fr1; o[nt][3] *= fr1;
        }

        // O += P @ V  (P passes in registers; 3-pass)
#pragma unroll
        for (int ks2 = 0; ks2 < 8; ks2++) {
            u32 ph[4], pl[4];
            ph[0] = pk2(s[2 * ks2][0],     s[2 * ks2][1]);
            ph[1] = pk2(s[2 * ks2][2],     s[2 * ks2][3]);
            ph[2] = pk2(s[2 * ks2 + 1][0], s[2 * ks2 + 1][1]);
            ph[3] = pk2(s[2 * ks2 + 1][2], s[2 * ks2 + 1][3]);
#pragma unroll
            for (int q = 0; q < 4; q++) {
                const float* sp = &s[2 * ks2 + (q >> 1)][(q & 1) * 2];
                float f0 = __uint_as_float(ph[q] << 16);
                float f1 = __uint_as_float(ph[q] & 0xffff0000u);
                pl[q] = pk2(sp[0] - f0, sp[1] - f1);
            }
#pragma unroll
            for (int np2 = 0; np2 < 4; np2++) {
                u32 va = stg + (u32)((ks2 * 16 + vrow_l) * ARS + np2 * 32 + vcol_l);
                u32 h0, h1, h2, h3, e0, e1, e2, e3;
                ldsm4t(h0, h1, h2, h3, va + AK_VH);
                ldsm4t(e0, e1, e2, e3, va + AK_VL);
                mma16816(o[2 * np2],     ph, h0, h1);
                mma16816(o[2 * np2 + 1], ph, h2, h3);
                mma16816(o[2 * np2],     pl, h0, h1);
                mma16816(o[2 * np2 + 1], pl, h2, h3);
                mma16816(o[2 * np2],     ph, e0, e1);
                mma16816(o[2 * np2 + 1], ph, e2, e3);
            }
        }
        __syncthreads();   // stage fully consumed
        if (kt + 2 < 16) {
            attn_cp_tile(sb + (kt & 1) * ASTG, row0 + (kt + 2) * 128, hcol, t);
            asm volatile("cp.async.commit_group;" ::: "memory");
        }
    }

    // epilogue: normalize, write ctx as bf16 hi/lo
    float inv0 = 1.0f / l0, inv1 = 1.0f / l1;
    int r0 = row0 + q0 + w * 16 + gid;
#pragma unroll
    for (int nt = 0; nt < 8; nt++) {
        int cc = hcol + nt * 8 + tig * 2;
        hilo_store(g_Chi, g_Clo, (size_t)r0 * DMODEL + cc,
                   o[nt][0] * inv0, o[nt][1] * inv0);
        hilo_store(g_Chi, g_Clo, (size_t)(r0 + 8) * DMODEL + cc,
                   o[nt][2] * inv1, o[nt][3] * inv1);
    }
}

// ---------------- launch ----------------
extern "C" void kernel_launch(void* const* d_in, const int* in_sizes, int n_in,
                              void* d_out, int out_size) {
    const float* X   = (const float*)d_in[0];
    const float* Wq  = (const float*)d_in[1];
    const float* Wk  = (const float*)d_in[2];
    const float* Wv  = (const float*)d_in[3];
    const float* Wo  = (const float*)d_in[4];
    const float* rbi = (const float*)d_in[5];
    float* out = (float*)d_out;

    cudaFuncSetAttribute(gemm_qkv_mma, cudaFuncAttributeMaxDynamicSharedMemorySize,
                         GEMM_SMEM);
    cudaFuncSetAttribute(gemm_o_mma, cudaFuncAttributeMaxDynamicSharedMemorySize,
                         GEMM_SMEM);
    cudaFuncSetAttribute(attn_mma_kernel, cudaFuncAttributeMaxDynamicSharedMemorySize,
                         ATTN_SMEM);

    bias_table_kernel<<<(HEADS * 4095 + 255) / 256, 256>>>(rbi);
    wconv_kernel<<<dim3(32, 32, 4), dim3(32, 8)>>>(Wq, Wk, Wv, Wo);
    xsplit_kernel<<<MROWS * DMODEL / 1024, 256>>>(X);

    gemm_qkv_mma<<<dim3(12, MROWS / 128), 256, GEMM_SMEM>>>();

    attn_mma_kernel<<<dim3(SEQ / 128, BATCH * HEADS), 256, ATTN_SMEM>>>();

    gemm_o_mma<<<dim3(DMODEL / 256, MROWS / 128), 256, GEMM_SMEM>>>(out);
}